// round 5
// baseline (speedup 1.0000x reference)
#include <cuda_runtime.h>
#include <cstdint>

// ---------------- problem constants ----------------
#define R    2048   // reservoir
#define Bz   16     // batch
#define Tn   2048   // timesteps
#define NO   3      // output size
#define CAP  384    // max padded nnz per row (mean 205, 13 sigma margin)
#define NBLK 148    // persistent blocks (<= SM count on B300/GB300)
#define WPB  14     // warps per block -> 148*14 = 2072 warps >= 2048 rows
#define TPB  (WPB * 32)

// ---------------- device scratch (static; no runtime alloc) ----------------
__device__ uint2    g_pairs[(size_t)R * CAP];            // (col, val-bits) CSR, padded to mult of 8
__device__ int      g_n8[R];                             // padded nnz / 8 per row
__device__ float    g_hs[(size_t)(Tn + 1) * R * Bz];     // state history, slot 0 = zeros. [t][r][b]
__device__ unsigned g_count;                             // monotonic barrier arrivals
__device__ unsigned g_gen;                               // completed step count

// ---------------- kernel 1: build padded CSR (deterministic, ballot compaction) ----------------
__global__ void build_csr(const float* __restrict__ W) {
    if (blockIdx.x == 0 && threadIdx.x == 0) { g_count = 0u; g_gen = 0u; }
    int warp = (blockIdx.x * blockDim.x + threadIdx.x) >> 5;
    int lane = threadIdx.x & 31;
    if (warp >= R) return;
    const int r = warp;
    const float* wrow = W + (size_t)r * R;
    uint2* prow = g_pairs + (size_t)r * CAP;

    int base = 0;
    for (int c0 = 0; c0 < R; c0 += 32) {
        float w = wrow[c0 + lane];
        unsigned m = __ballot_sync(0xffffffffu, w != 0.0f);
        if (w != 0.0f) {
            int pos = base + __popc(m & ((1u << lane) - 1u));
            if (pos < CAP)
                prow[pos] = make_uint2((unsigned)(c0 + lane), __float_as_uint(w));
        }
        base += __popc(m);
    }
    if (base > CAP) base = CAP;
    int padded = (base + 7) & ~7;
    for (int p = base + lane; p < padded; p += 32)
        prow[p] = make_uint2(0u, 0u);          // zero-value padding: harmless FMAs on h[0]
    if (lane == 0) g_n8[r] = padded >> 3;
    // zero h_0 slice for this row
    if (lane < Bz) g_hs[(size_t)r * Bz + lane] = 0.0f;
}

// ---------------- fast tanh (abs err ~1e-6, clamped -> no inf/nan) ----------------
__device__ __forceinline__ float tanh_fast(float v) {
    v = fminf(fmaxf(v, -12.0f), 12.0f);
    float e = __expf(2.0f * v);
    return __fdividef(e - 1.0f, e + 1.0f);
}

// ---------------- kernel 2: persistent recurrence over all T steps ----------------
// One warp per reservoir row. Lane layout: s = lane>>2 (8 k-slices), bq = lane&3 (4 batch-quads).
// Per nonzero: broadcast (col,val) to 4 bq-lanes, each loads float4 h[col][bq*4..+3] -> 16 batches.
__global__ __launch_bounds__(TPB, 1) void esn_steps(const float* __restrict__ x,
                                                    const float* __restrict__ Win) {
    const int tid  = threadIdx.x;
    const int w    = tid >> 5;
    const int lane = tid & 31;
    const int s    = lane >> 2;
    const int bq   = lane & 3;
    const int r    = blockIdx.x * WPB + w;
    const bool active = (r < R);

    __shared__ float xs[2][Bz * 3];   // double-buffered x_t staging

    float w0 = 0.f, w1 = 0.f, w2 = 0.f;
    int n8 = 0;
    const uint2* prow = g_pairs;
    if (active) {
        w0 = Win[r * 3 + 0];
        w1 = Win[r * 3 + 1];
        w2 = Win[r * 3 + 2];
        n8 = g_n8[r];
        prow = g_pairs + (size_t)r * CAP + s;   // this lane's k-slice stream
    }

    const float4* hs4 = (const float4*)g_hs;
    float4*       hw4 = (float4*)g_hs;

    for (int t = 0; t < Tn; ++t) {
        // stage x[:, t, :] (48 floats) into smem
        if (tid < Bz * 3) {
            int b = tid / 3, i = tid - b * 3;
            xs[t & 1][tid] = x[((size_t)b * Tn + t) * 3 + i];
        }
        // wait until hs[t] is fully written by all blocks (step t-1 complete)
        if (t > 0 && tid == 0) {
            while (*(volatile unsigned*)&g_gen < (unsigned)t) { }
            __threadfence();
        }
        __syncthreads();

        if (active) {
            const float4* hp = hs4 + (size_t)t * (R * Bz / 4);
            float4 acc = make_float4(0.f, 0.f, 0.f, 0.f);
            #pragma unroll 4
            for (int k = 0; k < n8; ++k) {
                uint2  pr  = __ldg(prow + (k << 3));
                float  val = __uint_as_float(pr.y);
                float4 hv  = __ldg(hp + ((size_t)pr.x * 4 + bq));
                acc.x = fmaf(val, hv.x, acc.x);
                acc.y = fmaf(val, hv.y, acc.y);
                acc.z = fmaf(val, hv.z, acc.z);
                acc.w = fmaf(val, hv.w, acc.w);
            }
            // reduce across the 8 k-slices (bq preserved)
            #pragma unroll
            for (int off = 16; off >= 4; off >>= 1) {
                acc.x += __shfl_xor_sync(0xffffffffu, acc.x, off);
                acc.y += __shfl_xor_sync(0xffffffffu, acc.y, off);
                acc.z += __shfl_xor_sync(0xffffffffu, acc.z, off);
                acc.w += __shfl_xor_sync(0xffffffffu, acc.w, off);
            }
            if (s == 0) {   // lanes 0..3 hold batches bq*4 .. bq*4+3
                const float* xc = xs[t & 1];
                const int b0 = bq * 4;
                float4 o;
                o.x = tanh_fast(acc.x + xc[(b0+0)*3]*w0 + xc[(b0+0)*3+1]*w1 + xc[(b0+0)*3+2]*w2);
                o.y = tanh_fast(acc.y + xc[(b0+1)*3]*w0 + xc[(b0+1)*3+1]*w1 + xc[(b0+1)*3+2]*w2);
                o.z = tanh_fast(acc.z + xc[(b0+2)*3]*w0 + xc[(b0+2)*3+1]*w1 + xc[(b0+2)*3+2]*w2);
                o.w = tanh_fast(acc.w + xc[(b0+3)*3]*w0 + xc[(b0+3)*3+1]*w1 + xc[(b0+3)*3+2]*w2);
                hw4[(size_t)(t + 1) * (R * Bz / 4) + (size_t)r * 4 + bq] = o;
            }
        }
        // publish this block's hs[t+1] writes, then arrive
        __threadfence();
        __syncthreads();
        if (tid == 0) {
            unsigned a = atomicAdd(&g_count, 1u);
            if (a == (unsigned)(t + 1) * NBLK - 1u) {
                __threadfence();
                *(volatile unsigned*)&g_gen = (unsigned)(t + 1);
            }
        }
    }
}

// ---------------- kernel 3: out[b][t][o] = hs[t+1] . Wout[o] + bias[o] ----------------
__global__ void esn_out(const float* __restrict__ Wout_w,
                        const float* __restrict__ Wout_b,
                        float* __restrict__ out) {
    const int t   = blockIdx.x;
    const int tid = threadIdx.x;
    const float* h = g_hs + (size_t)(t + 1) * R * Bz;

    const int b = tid & 15;     // batch
    const int g = tid >> 4;     // r-group 0..15
    float a0 = 0.f, a1 = 0.f, a2 = 0.f;
    for (int r = g; r < R; r += 16) {
        float hv = __ldg(h + (size_t)r * Bz + b);
        a0 = fmaf(hv, __ldg(Wout_w + r),         a0);
        a1 = fmaf(hv, __ldg(Wout_w + R + r),     a1);
        a2 = fmaf(hv, __ldg(Wout_w + 2 * R + r), a2);
    }
    __shared__ float red[256][3];
    red[tid][0] = a0; red[tid][1] = a1; red[tid][2] = a2;
    __syncthreads();
    if (tid < Bz * NO) {
        int bb = tid / 3, o = tid - bb * 3;
        float sum = 0.f;
        #pragma unroll
        for (int gg = 0; gg < 16; ++gg) sum += red[gg * 16 + bb][o];
        out[((size_t)bb * Tn + t) * 3 + o] = sum + Wout_b[o];
    }
}

// ---------------- launch ----------------
extern "C" void kernel_launch(void* const* d_in, const int* in_sizes, int n_in,
                              void* d_out, int out_size) {
    const float* x      = (const float*)d_in[0];  // [16, 2048, 3]
    const float* Win    = (const float*)d_in[1];  // [2048, 3]
    const float* W      = (const float*)d_in[2];  // [2048, 2048]
    const float* Wout_w = (const float*)d_in[3];  // [3, 2048]
    const float* Wout_b = (const float*)d_in[4];  // [3]
    float* out = (float*)d_out;                   // [16, 2048, 3]

    (void)in_sizes; (void)n_in; (void)out_size;

    // 1) sparsify W into padded CSR + zero h_0 + reset barrier state (every replay)
    build_csr<<<(R * 32 + 255) / 256, 256>>>(W);
    // 2) persistent recurrence, 2048 internal grid barriers
    esn_steps<<<NBLK, TPB>>>(x, Win);
    // 3) readout projection
    esn_out<<<Tn, 256>>>(Wout_w, Wout_b, out);
}

// round 6
// speedup vs baseline: 1.3443x; 1.3443x over previous
#include <cuda_runtime.h>
#include <cstdint>

// ---------------- problem constants ----------------
#define R    2048   // reservoir
#define Bz   16     // batch
#define Tn   2048   // timesteps
#define NO   3      // output size
#define KPAD 288    // UNIFORM padded nnz per row (mean 205, sd 13.6 -> +6.1 sigma)
#define K8   (KPAD / 8)   // 36 register pairs per lane (8 k-slices per warp)
#define NBLK 148    // persistent blocks (<= SM count on B300/GB300)
#define WPB  14     // warps per block -> one row per warp, 148*14 = 2072 >= 2048
#define TPB  (WPB * 32)

// ---------------- device scratch (static; no runtime alloc) ----------------
__device__ uint2    g_pairs[(size_t)R * KPAD];          // (col, val-bits), zero-padded to KPAD
__device__ float    g_hs[(size_t)(Tn + 1) * R * Bz];    // state history, slot 0 = zeros. [t][r][b]
__device__ unsigned g_flag[160];                        // per-block completed-step counters
                                                        // [148..159] pinned to 0xFFFFFFFF

// ---------------- kernel 1: build UNIFORMLY padded CSR + reset flags + zero h0 ----------------
__global__ void build_csr(const float* __restrict__ W) {
    int gt = blockIdx.x * blockDim.x + threadIdx.x;
    if (gt < 160) g_flag[gt] = (gt < NBLK) ? 0u : 0xFFFFFFFFu;

    int warp = gt >> 5;
    int lane = threadIdx.x & 31;
    if (warp >= R) return;
    const int r = warp;
    const float* wrow = W + (size_t)r * R;
    uint2* prow = g_pairs + (size_t)r * KPAD;

    int base = 0;
    for (int c0 = 0; c0 < R; c0 += 32) {
        float w = wrow[c0 + lane];
        unsigned m = __ballot_sync(0xffffffffu, w != 0.0f);
        if (w != 0.0f) {
            int pos = base + __popc(m & ((1u << lane) - 1u));
            if (pos < KPAD)
                prow[pos] = make_uint2((unsigned)(c0 + lane), __float_as_uint(w));
        }
        base += __popc(m);
    }
    if (base > KPAD) base = KPAD;
    // zero-value padding up to KPAD: harmless FMAs against h[0], coalesces to one line
    for (int p = base + lane; p < KPAD; p += 32)
        prow[p] = make_uint2(0u, 0u);
    // zero h_0 slice for this row
    if (lane < Bz) g_hs[(size_t)r * Bz + lane] = 0.0f;
}

// ---------------- fast tanh (abs err ~1e-6, clamped -> no inf/nan) ----------------
__device__ __forceinline__ float tanh_fast(float v) {
    v = fminf(fmaxf(v, -12.0f), 12.0f);
    float e = __expf(2.0f * v);
    return __fdividef(e - 1.0f, e + 1.0f);
}

// ---------------- kernel 2: persistent recurrence ----------------
// One warp per row. lane = s (k-slice, 0..7) x bq (batch-quad, 0..3).
// W pairs are STEP-INVARIANT -> hoisted into registers once; per step each lane
// issues K8 fully-independent LDG.128 gathers of h[col][bq*4..+3].
__global__ __launch_bounds__(TPB, 1) void esn_steps(const float* __restrict__ x,
                                                    const float* __restrict__ Win) {
    const int tid  = threadIdx.x;
    const int w    = tid >> 5;
    const int lane = tid & 31;
    const int s    = lane >> 2;
    const int bq   = lane & 3;
    const int r    = blockIdx.x * WPB + w;
    const bool active = (r < R);

    __shared__ float xs[2][Bz * 3];

    // hoist W row (this lane's k-slice stream) into registers
    unsigned off[K8];
    float    val[K8];
    float w0 = 0.f, w1 = 0.f, w2 = 0.f;
    if (active) {
        w0 = Win[r * 3 + 0];
        w1 = Win[r * 3 + 1];
        w2 = Win[r * 3 + 2];
        const uint2* p = g_pairs + (size_t)r * KPAD + s;
        #pragma unroll
        for (int k = 0; k < K8; ++k) {
            uint2 pr = __ldg(p + (k << 3));
            off[k] = pr.x * (Bz * 4) + bq * 16;   // byte offset into h slice
            val[k] = __uint_as_float(pr.y);
        }
    } else {
        #pragma unroll
        for (int k = 0; k < K8; ++k) { off[k] = (unsigned)(bq * 16); val[k] = 0.f; }
    }

    for (int t = 0; t < Tn; ++t) {
        // stage x[:, t, :] (48 floats) — independent of h, do it before the wait
        if (tid < Bz * 3) {
            int b = tid / 3, i = tid - b * 3;
            xs[t & 1][tid] = x[((size_t)b * Tn + t) * 3 + i];
        }
        // wait until all blocks have published step t-1 (flags >= t)
        if (t > 0) {
            if (tid < 32) {
                const unsigned tgt = (unsigned)t;
                const unsigned* f = g_flag;
                for (;;) {
                    unsigned a0, a1, a2, a3, a4;
                    asm volatile("ld.acquire.gpu.global.b32 %0,[%1];" : "=r"(a0) : "l"(f + lane));
                    asm volatile("ld.acquire.gpu.global.b32 %0,[%1];" : "=r"(a1) : "l"(f + lane + 32));
                    asm volatile("ld.acquire.gpu.global.b32 %0,[%1];" : "=r"(a2) : "l"(f + lane + 64));
                    asm volatile("ld.acquire.gpu.global.b32 %0,[%1];" : "=r"(a3) : "l"(f + lane + 96));
                    asm volatile("ld.acquire.gpu.global.b32 %0,[%1];" : "=r"(a4) : "l"(f + lane + 128));
                    bool ok = (a0 >= tgt) & (a1 >= tgt) & (a2 >= tgt) & (a3 >= tgt) & (a4 >= tgt);
                    if (__all_sync(0xffffffffu, ok)) break;
                }
            }
        }
        __syncthreads();

        // gather + FMA: all K8 loads independent (addresses are register-resident)
        const char* hb = (const char*)g_hs + (size_t)t * (R * Bz * 4);
        float4 acc = make_float4(0.f, 0.f, 0.f, 0.f);
        #pragma unroll
        for (int k = 0; k < K8; ++k) {
            float4 hv = __ldg((const float4*)(hb + off[k]));
            acc.x = fmaf(val[k], hv.x, acc.x);
            acc.y = fmaf(val[k], hv.y, acc.y);
            acc.z = fmaf(val[k], hv.z, acc.z);
            acc.w = fmaf(val[k], hv.w, acc.w);
        }
        // reduce across the 8 k-slices (bq preserved)
        #pragma unroll
        for (int o = 16; o >= 4; o >>= 1) {
            acc.x += __shfl_xor_sync(0xffffffffu, acc.x, o);
            acc.y += __shfl_xor_sync(0xffffffffu, acc.y, o);
            acc.z += __shfl_xor_sync(0xffffffffu, acc.z, o);
            acc.w += __shfl_xor_sync(0xffffffffu, acc.w, o);
        }
        if (active && s == 0) {   // lanes 0..3 hold batches bq*4 .. bq*4+3
            const float* xc = xs[t & 1];
            const int b0 = bq * 4;
            float4 o4;
            o4.x = tanh_fast(acc.x + xc[(b0+0)*3]*w0 + xc[(b0+0)*3+1]*w1 + xc[(b0+0)*3+2]*w2);
            o4.y = tanh_fast(acc.y + xc[(b0+1)*3]*w0 + xc[(b0+1)*3+1]*w1 + xc[(b0+1)*3+2]*w2);
            o4.z = tanh_fast(acc.z + xc[(b0+2)*3]*w0 + xc[(b0+2)*3+1]*w1 + xc[(b0+2)*3+2]*w2);
            o4.w = tanh_fast(acc.w + xc[(b0+3)*3]*w0 + xc[(b0+3)*3+1]*w1 + xc[(b0+3)*3+2]*w2);
            *(float4*)((char*)g_hs + (size_t)(t + 1) * (R * Bz * 4) + (size_t)r * 64 + bq * 16) = o4;
        }
        // all warps done writing h[t+1] slice -> publish with a release store (no membar)
        __syncthreads();
        if (tid == 0) {
            unsigned nv = (unsigned)(t + 1);
            asm volatile("st.release.gpu.global.b32 [%0], %1;"
                         :: "l"(g_flag + blockIdx.x), "r"(nv) : "memory");
        }
    }
}

// ---------------- kernel 3: out[b][t][o] = hs[t+1] . Wout[o] + bias[o] ----------------
__global__ void esn_out(const float* __restrict__ Wout_w,
                        const float* __restrict__ Wout_b,
                        float* __restrict__ out) {
    const int t   = blockIdx.x;
    const int tid = threadIdx.x;
    const float* h = g_hs + (size_t)(t + 1) * R * Bz;

    const int b = tid & 15;     // batch
    const int g = tid >> 4;     // r-group 0..15
    float a0 = 0.f, a1 = 0.f, a2 = 0.f;
    for (int r = g; r < R; r += 16) {
        float hv = __ldg(h + (size_t)r * Bz + b);
        a0 = fmaf(hv, __ldg(Wout_w + r),         a0);
        a1 = fmaf(hv, __ldg(Wout_w + R + r),     a1);
        a2 = fmaf(hv, __ldg(Wout_w + 2 * R + r), a2);
    }
    __shared__ float red[256][3];
    red[tid][0] = a0; red[tid][1] = a1; red[tid][2] = a2;
    __syncthreads();
    if (tid < Bz * NO) {
        int bb = tid / 3, o = tid - bb * 3;
        float sum = 0.f;
        #pragma unroll
        for (int gg = 0; gg < 16; ++gg) sum += red[gg * 16 + bb][o];
        out[((size_t)bb * Tn + t) * 3 + o] = sum + Wout_b[o];
    }
}

// ---------------- launch ----------------
extern "C" void kernel_launch(void* const* d_in, const int* in_sizes, int n_in,
                              void* d_out, int out_size) {
    const float* x      = (const float*)d_in[0];  // [16, 2048, 3]
    const float* Win    = (const float*)d_in[1];  // [2048, 3]
    const float* W      = (const float*)d_in[2];  // [2048, 2048]
    const float* Wout_w = (const float*)d_in[3];  // [3, 2048]
    const float* Wout_b = (const float*)d_in[4];  // [3]
    float* out = (float*)d_out;                   // [16, 2048, 3]

    (void)in_sizes; (void)n_in; (void)out_size;

    build_csr<<<(R * 32 + 255) / 256, 256>>>(W);   // uniform-pad CSR + flag/h0 reset
    esn_steps<<<NBLK, TPB>>>(x, Win);              // 2048 steps, flag-barrier per step
    esn_out<<<Tn, 256>>>(Wout_w, Wout_b, out);     // readout projection
}